// round 14
// baseline (speedup 1.0000x reference)
#include <cuda_runtime.h>
#include <cuda_fp16.h>
#include <math.h>
#include <stdint.h>

// Problem constants
#define Bb     32
#define Dd     64
#define Kk     512
#define DHW    262144        // D*H*W
#define Nn     131072        // B*H*W
#define EPSf   1e-5f
#define NTILES 1024          // 128-row tiles
#define GRID_P 148           // persistent CTAs (= #SMs, occupancy 1)

// ---------------------------------------------------------------------------
// Helpers
// ---------------------------------------------------------------------------
__device__ __forceinline__ uint32_t smem_to_u32(const void* p) {
    uint32_t a;
    asm("{ .reg .u64 t; cvta.to.shared.u64 t, %1; cvt.u32.u64 %0, t; }" : "=r"(a) : "l"(p));
    return a;
}
__device__ __forceinline__ void f16_split2(float a, float b, uint32_t& hi, uint32_t& lo) {
    __half ha = __float2half_rn(a), hb = __float2half_rn(b);
    float  ra = a - __half2float(ha), rb = b - __half2float(hb);
    __half la = __float2half_rn(ra), lb = __float2half_rn(rb);
    __half2 h = __halves2half2(ha, hb), l = __halves2half2(la, lb);
    hi = *(uint32_t*)&h;
    lo = *(uint32_t*)&l;
}
__device__ __forceinline__ void mma_f16(float* c, const uint32_t* a, uint32_t b0, uint32_t b1) {
    asm volatile("mma.sync.aligned.m16n8k16.row.col.f32.f16.f16.f32 "
        "{%0,%1,%2,%3}, {%4,%5,%6,%7}, {%8,%9}, {%0,%1,%2,%3};"
        : "+f"(c[0]), "+f"(c[1]), "+f"(c[2]), "+f"(c[3])
        : "r"(a[0]), "r"(a[1]), "r"(a[2]), "r"(a[3]), "r"(b0), "r"(b1));
}
#define CP_ASYNC16(s, g) asm volatile("cp.async.cg.shared.global [%0], [%1], 16;" :: "r"(s), "l"(g))
#define CP_COMMIT()      asm volatile("cp.async.commit_group;" ::: "memory")
#define CP_WAIT0()       asm volatile("cp.async.wait_group 0;" ::: "memory")

// ---------------------------------------------------------------------------
// Scratch
// ---------------------------------------------------------------------------
__device__ float d_ec[Kk];
__device__ int   d_counts[Kk];
__device__ float d_sums[Dd * Kk];
__device__ uint4 g_frag[8192];
// grid barrier state (generation counter is monotonic across launches)
__device__ unsigned g_bar = 0;
__device__ unsigned g_gen = 0;

// cooperative-groups-style software grid sync (all GRID_P CTAs co-resident)
__device__ __forceinline__ void grid_sync(int tid) {
    __threadfence();
    __syncthreads();
    if (tid == 0) {
        unsigned snap = *(volatile unsigned*)&g_gen;   // pre-arrive snapshot
        unsigned old  = atomicAdd(&g_bar, 1u);
        if (old == GRID_P - 1) {
            atomicExch(&g_bar, 0u);
            __threadfence();
            atomicAdd(&g_gen, 1u);
        } else {
            while (*(volatile unsigned*)&g_gen == snap) __nanosleep(64);
        }
        __threadfence();
    }
    __syncthreads();
}

// ---------------------------------------------------------------------------
// SMEM layout (bytes): x tiles [d(64)][132 f32], double buffered
// ---------------------------------------------------------------------------
#define XLD       132
#define SM_X0     0                        // 33792
#define SM_X1     33792                    // 33792
#define SM_EC     67584                    // 2048
#define SM_BEST   69632                    // 2048
#define SM_IDXH   71680                    // 2048
#define SM_SIDX   73728                    // 512
#define SM_SQ     74240                    // 18944
#define SM_FRAG   93184                    // 131072
#define SM_TOTAL  224256

// one n-pair MMA + argmin iteration (np = NPV)
#define NP_ONE(NPV) {                                                          \
    int ntA = (qtr << 4) + 2 * (NPV);                                          \
    float acc[4][4] = {{0.f,0.f,0.f,0.f},{0.f,0.f,0.f,0.f},                    \
                       {0.f,0.f,0.f,0.f},{0.f,0.f,0.f,0.f}};                   \
    _Pragma("unroll")                                                          \
    for (int ks = 0; ks < 4; ks++) {                                           \
        uint32_t a0 = sb + SM_FRAG + ((((ntA << 2) + ks) << 5) + lid) * 16;    \
        uint4 bA, bB;                                                          \
        asm volatile("ld.shared.v4.b32 {%0,%1,%2,%3}, [%4];"                   \
            : "=r"(bA.x), "=r"(bA.y), "=r"(bA.z), "=r"(bA.w) : "r"(a0));       \
        asm volatile("ld.shared.v4.b32 {%0,%1,%2,%3}, [%4];"                   \
            : "=r"(bB.x), "=r"(bB.y), "=r"(bB.z), "=r"(bB.w) : "r"(a0 + 2048));\
        const uint32_t* ah0 = &Ahi[ks * 4];                                    \
        const uint32_t* al0 = &Alo[ks * 4];                                    \
        const uint32_t* ah1 = &Ahi[16 + ks * 4];                               \
        const uint32_t* al1 = &Alo[16 + ks * 4];                               \
        mma_f16(acc[0], ah0, bA.x, bA.y);                                      \
        mma_f16(acc[1], ah0, bB.x, bB.y);                                      \
        mma_f16(acc[2], ah1, bA.x, bA.y);                                      \
        mma_f16(acc[3], ah1, bB.x, bB.y);                                      \
        mma_f16(acc[0], ah0, bA.z, bA.w);                                      \
        mma_f16(acc[1], ah0, bB.z, bB.w);                                      \
        mma_f16(acc[2], ah1, bA.z, bA.w);                                      \
        mma_f16(acc[3], ah1, bB.z, bB.w);                                      \
        mma_f16(acc[0], al0, bA.x, bA.y);                                      \
        mma_f16(acc[1], al0, bB.x, bB.y);                                      \
        mma_f16(acc[2], al1, bA.x, bA.y);                                      \
        mma_f16(acc[3], al1, bB.x, bB.y);                                      \
    }                                                                          \
    int base0 = ntA * 8 + 2 * tig;                                             \
    float2 e0 = *(float2*)(sec + base0);                                       \
    float2 e1 = *(float2*)(sec + base0 + 8);                                   \
    float s;                                                                   \
    s = fmaf(acc[0][0], -2.f, e0.x); if (s < best[0]) { best[0] = s; idx[0] = base0; }     \
    s = fmaf(acc[0][1], -2.f, e0.y); if (s < best[0]) { best[0] = s; idx[0] = base0 + 1; } \
    s = fmaf(acc[0][2], -2.f, e0.x); if (s < best[1]) { best[1] = s; idx[1] = base0; }     \
    s = fmaf(acc[0][3], -2.f, e0.y); if (s < best[1]) { best[1] = s; idx[1] = base0 + 1; } \
    s = fmaf(acc[1][0], -2.f, e1.x); if (s < best[0]) { best[0] = s; idx[0] = base0 + 8; } \
    s = fmaf(acc[1][1], -2.f, e1.y); if (s < best[0]) { best[0] = s; idx[0] = base0 + 9; } \
    s = fmaf(acc[1][2], -2.f, e1.x); if (s < best[1]) { best[1] = s; idx[1] = base0 + 8; } \
    s = fmaf(acc[1][3], -2.f, e1.y); if (s < best[1]) { best[1] = s; idx[1] = base0 + 9; } \
    s = fmaf(acc[2][0], -2.f, e0.x); if (s < best[2]) { best[2] = s; idx[2] = base0; }     \
    s = fmaf(acc[2][1], -2.f, e0.y); if (s < best[2]) { best[2] = s; idx[2] = base0 + 1; } \
    s = fmaf(acc[2][2], -2.f, e0.x); if (s < best[3]) { best[3] = s; idx[3] = base0; }     \
    s = fmaf(acc[2][3], -2.f, e0.y); if (s < best[3]) { best[3] = s; idx[3] = base0 + 1; } \
    s = fmaf(acc[3][0], -2.f, e1.x); if (s < best[2]) { best[2] = s; idx[2] = base0 + 8; } \
    s = fmaf(acc[3][1], -2.f, e1.y); if (s < best[2]) { best[2] = s; idx[2] = base0 + 9; } \
    s = fmaf(acc[3][2], -2.f, e1.x); if (s < best[3]) { best[3] = s; idx[3] = base0 + 8; } \
    s = fmaf(acc[3][3], -2.f, e1.y); if (s < best[3]) { best[3] = s; idx[3] = base0 + 9; } \
}

__device__ __forceinline__ int decode_scalar_int(const int* p) {
    int v = *p;
    if (v >= 0 && v < 1000000) return v;
    return (int)__int_as_float(v);
}

// ---------------------------------------------------------------------------
// Single persistent kernel: prep slice -> grid sync -> GEMM+argmin+outputs
// (pipelined epilogue) -> grid sync -> fused norm+weight.
// ---------------------------------------------------------------------------
__global__ __launch_bounds__(512, 1)
void vq_kernel(const float* __restrict__ x,
               const float* __restrict__ emb,
               const float* __restrict__ ema_c,
               const float* __restrict__ ema_e,
               const int* __restrict__ counter,
               const int* __restrict__ training,
               float* __restrict__ q,
               float* __restrict__ w) {
    extern __shared__ char smem[];
    uint32_t sb = smem_to_u32(smem);
    int tid = threadIdx.x;
    int wid = tid >> 5;
    int lid = tid & 31;
    int grp = lid >> 2;
    int tig = lid & 3;
    int qtr = wid & 3;
    int rws = wid >> 2;

    float* sec   = (float*)(smem + SM_EC);
    float* sbest = (float*)(smem + SM_BEST);
    int*   sidxh = (int*)(smem + SM_IDXH);
    int*   sidx  = (int*)(smem + SM_SIDX);
    float* sq    = (float*)(smem + SM_SQ);

    int er = tid >> 3, ec_ = tid & 7;
    int edd = tid >> 5, eg = tid & 31;

    // ---- first x tile (independent of prep; overlaps it) ----
    {
        int t0  = blockIdx.x;
        const float* xb = x + (size_t)(t0 >> 5) * DHW + ((t0 & 31) << 7);
#pragma unroll
        for (int jj = 0; jj < 4; jj++) {
            int i = tid + jj * 512;
            int d = i >> 5, r4 = (i & 31) << 2;
            CP_ASYNC16(sb + SM_X0 + (d * XLD + r4) * 4,
                       (const char*)(xb + (d << 12) + r4));
        }
        CP_COMMIT();
    }

    // ---- prep slice (1/148 of work per CTA) ----
    if (tid < 56) {
        int i = blockIdx.x * 56 + tid;                 // 0..8287, use < 8192
        if (i < 8192) {
            ((float4*)d_sums)[i] = make_float4(0.f, 0.f, 0.f, 0.f);
            float4 v = __ldg((const float4*)emb + i);
            int code = i >> 4, k = (i & 15) << 2;
            uint32_t* gf = (uint32_t*)g_frag;
            int nt = code >> 3;
#pragma unroll
            for (int p = 0; p < 2; p++) {
                int   k0 = k + 2 * p;
                float a  = p ? v.z : v.x;
                float b  = p ? v.w : v.y;
                uint32_t hi, lo;
                f16_split2(a, b, hi, lo);
                int rem  = k0 & 15;
                int slot = rem >> 3;
                int sel  = (rem & 7) >> 1;
                int ks   = k0 >> 4;
                int entry = nt * 128 + ks * 32 + ((code & 7) << 2) + sel;
                gf[entry * 4 + slot]     = hi;
                gf[entry * 4 + 2 + slot] = lo;
            }
        }
    }
    if (tid < 4) {
        int c = blockIdx.x * 4 + tid;
        if (c < Kk) d_counts[c] = 0;
    }
    {   // ||e_k||^2: one warp per code
        int gw = blockIdx.x * 16 + wid;
        if (gw < Kk) {
            float a = __ldg(emb + gw * 64 + lid);
            float b = __ldg(emb + gw * 64 + 32 + lid);
            float s = a * a + b * b;
#pragma unroll
            for (int o = 16; o > 0; o >>= 1) s += __shfl_xor_sync(0xffffffffu, s, o);
            if (lid == 0) d_ec[gw] = s;
        }
    }

    grid_sync(tid);

    // ---- load fragments + ec into SMEM ----
#pragma unroll
    for (int jj = 0; jj < 16; jj++) {
        int i = tid + jj * 512;
        CP_ASYNC16(sb + SM_FRAG + i * 16, (const char*)g_frag + i * 16);
    }
    sec[tid] = d_ec[tid];
    CP_COMMIT();
    CP_WAIT0();
    __syncthreads();

    // ---- persistent tile loop (identical to R13 hot path) ----
    int j = 0;
    int bp = 0, hwp = 0;
    for (int t = blockIdx.x; t < NTILES; t += GRID_P, j++) {
        float* sxc = (float*)(smem + ((j & 1) ? SM_X1 : SM_X0));
        float* sxp = (float*)(smem + ((j & 1) ? SM_X0 : SM_X1));
        uint32_t sxpb = sb + ((j & 1) ? SM_X0 : SM_X1);
        int b   = t >> 5;
        int hw0 = (t & 31) << 7;
        int tn  = t + GRID_P;
        bool hasPrev = (j > 0);
        float* qbp = q + (size_t)bp * DHW + hwp;

        uint32_t Ahi[32], Alo[32];
#pragma unroll
        for (int mt = 0; mt < 2; mt++) {
            int rb = rws * 32 + mt * 16 + grp;
#pragma unroll
            for (int ks = 0; ks < 4; ks++) {
                int kb = ks * 16 + tig * 2;
                int o  = mt * 16 + ks * 4;
                f16_split2(sxc[kb * XLD + rb],           sxc[(kb + 1) * XLD + rb],
                           Ahi[o + 0], Alo[o + 0]);
                f16_split2(sxc[kb * XLD + rb + 8],       sxc[(kb + 1) * XLD + rb + 8],
                           Ahi[o + 1], Alo[o + 1]);
                f16_split2(sxc[(kb + 8) * XLD + rb],     sxc[(kb + 9) * XLD + rb],
                           Ahi[o + 2], Alo[o + 2]);
                f16_split2(sxc[(kb + 8) * XLD + rb + 8], sxc[(kb + 9) * XLD + rb + 8],
                           Ahi[o + 3], Alo[o + 3]);
            }
        }

        if (!hasPrev && tn < NTILES) {
            const float* xb = x + (size_t)(tn >> 5) * DHW + ((tn & 31) << 7);
#pragma unroll
            for (int jj = 0; jj < 4; jj++) {
                int i = tid + jj * 512;
                int d = i >> 5, r4 = (i & 31) << 2;
                CP_ASYNC16(sxpb + (d * XLD + r4) * 4, (const char*)(xb + (d << 12) + r4));
            }
            CP_COMMIT();
        }

        float best[4] = {3.4e38f, 3.4e38f, 3.4e38f, 3.4e38f};
        int   idx[4]  = {0, 0, 0, 0};
        float4 epv0, epv1;

        NP_ONE(0) NP_ONE(1)
        if (hasPrev) {
            epv0 = __ldg((const float4*)(emb + sidx[er]      * 64 + ec_ * 4));
            epv1 = __ldg((const float4*)(emb + sidx[er + 64] * 64 + ec_ * 4));
        }
        NP_ONE(2) NP_ONE(3)
        if (hasPrev) {
            float* sp0 = sq + er * 37 + ec_ * 4;
            float* sp1 = sq + (er + 64) * 37 + ec_ * 4;
            sp0[0] = epv0.x; sp0[1] = epv0.y; sp0[2] = epv0.z; sp0[3] = epv0.w;
            sp1[0] = epv1.x; sp1[1] = epv1.y; sp1[2] = epv1.z; sp1[3] = epv1.w;
            int k0 = sidx[4 * eg], k1 = sidx[4 * eg + 1];
            int k2 = sidx[4 * eg + 2], k3 = sidx[4 * eg + 3];
#pragma unroll
            for (int hh = 0; hh < 4; hh++) {
                int d = edd + hh * 16;
                const float* xr = sxp + d * XLD + 4 * eg;
                atomicAdd(&d_sums[(d << 9) + k0], xr[0]);
                atomicAdd(&d_sums[(d << 9) + k1], xr[1]);
                atomicAdd(&d_sums[(d << 9) + k2], xr[2]);
                atomicAdd(&d_sums[(d << 9) + k3], xr[3]);
            }
        }
        __syncthreads();
        if (hasPrev && tn < NTILES) {
            const float* xb = x + (size_t)(tn >> 5) * DHW + ((tn & 31) << 7);
#pragma unroll
            for (int jj = 0; jj < 4; jj++) {
                int i = tid + jj * 512;
                int d = i >> 5, r4 = (i & 31) << 2;
                CP_ASYNC16(sxpb + (d * XLD + r4) * 4, (const char*)(xb + (d << 12) + r4));
            }
            CP_COMMIT();
        }
        NP_ONE(4) NP_ONE(5)
        if (hasPrev) {
#pragma unroll
            for (int it = 0; it < 2; it++) {
                int d = edd + it * 16;
                float4 ov;
                ov.x = sq[(4 * eg)     * 37 + d];
                ov.y = sq[(4 * eg + 1) * 37 + d];
                ov.z = sq[(4 * eg + 2) * 37 + d];
                ov.w = sq[(4 * eg + 3) * 37 + d];
                ((float4*)(qbp + (d << 12)))[eg] = ov;
            }
            epv0 = __ldg((const float4*)(emb + sidx[er]      * 64 + 32 + ec_ * 4));
            epv1 = __ldg((const float4*)(emb + sidx[er + 64] * 64 + 32 + ec_ * 4));
        }
        __syncthreads();
        NP_ONE(6) NP_ONE(7)
        if (hasPrev) {
            float* sp0 = sq + er * 37 + ec_ * 4;
            float* sp1 = sq + (er + 64) * 37 + ec_ * 4;
            sp0[0] = epv0.x; sp0[1] = epv0.y; sp0[2] = epv0.z; sp0[3] = epv0.w;
            sp1[0] = epv1.x; sp1[1] = epv1.y; sp1[2] = epv1.z; sp1[3] = epv1.w;
        }
        __syncthreads();
        if (hasPrev) {
#pragma unroll
            for (int it = 0; it < 2; it++) {
                int dd2 = edd + it * 16;
                int d = 32 + dd2;
                float4 ov;
                ov.x = sq[(4 * eg)     * 37 + dd2];
                ov.y = sq[(4 * eg + 1) * 37 + dd2];
                ov.z = sq[(4 * eg + 2) * 37 + dd2];
                ov.w = sq[(4 * eg + 3) * 37 + dd2];
                ((float4*)(qbp + (d << 12)))[eg] = ov;
            }
        }

#pragma unroll
        for (int v = 0; v < 4; v++) {
#pragma unroll
            for (int o = 1; o <= 2; o <<= 1) {
                float ob = __shfl_xor_sync(0xffffffffu, best[v], o);
                int   oi = __shfl_xor_sync(0xffffffffu, idx[v], o);
                if (ob < best[v] || (ob == best[v] && oi < idx[v])) { best[v] = ob; idx[v] = oi; }
            }
        }
        if (tig == 0) {
            int rl = rws * 32 + grp;
            sbest[qtr * 128 + rl]      = best[0];
            sbest[qtr * 128 + rl + 8]  = best[1];
            sbest[qtr * 128 + rl + 16] = best[2];
            sbest[qtr * 128 + rl + 24] = best[3];
            sidxh[qtr * 128 + rl]      = idx[0];
            sidxh[qtr * 128 + rl + 8]  = idx[1];
            sidxh[qtr * 128 + rl + 16] = idx[2];
            sidxh[qtr * 128 + rl + 24] = idx[3];
        }
        __syncthreads();
        if (tid < 128) {
            float bb = sbest[tid]; int ii = sidxh[tid];
#pragma unroll
            for (int qq = 1; qq < 4; qq++) {
                float b2 = sbest[qq * 128 + tid];
                if (b2 < bb) { bb = b2; ii = sidxh[qq * 128 + tid]; }
            }
            sidx[tid] = ii;
            atomicAdd(&d_counts[ii], 1);
        }
        bp = b; hwp = hw0;
        CP_WAIT0();
        __syncthreads();
    }

    // ---- final tile epilogue ----
    {
        float* sxl = (float*)(smem + (((j - 1) & 1) ? SM_X1 : SM_X0));
        float* qb  = q + (size_t)bp * DHW + hwp;
#pragma unroll
        for (int pass = 0; pass < 2; pass++) {
#pragma unroll
            for (int it = 0; it < 2; it++) {
                int item = tid + it * 512;
                int r = item >> 3, c = item & 7;
                int ki = sidx[r];
                float4 ev = __ldg((const float4*)(emb + ki * 64 + pass * 32 + c * 4));
                float* sp = sq + r * 37 + c * 4;
                sp[0] = ev.x; sp[1] = ev.y; sp[2] = ev.z; sp[3] = ev.w;
            }
            __syncthreads();
#pragma unroll
            for (int it = 0; it < 2; it++) {
                int item = tid + it * 512;
                int dd = item >> 5, g = item & 31;
                int d  = pass * 32 + dd;
                float4 ov;
                ov.x = sq[(4 * g)     * 37 + dd];
                ov.y = sq[(4 * g + 1) * 37 + dd];
                ov.z = sq[(4 * g + 2) * 37 + dd];
                ov.w = sq[(4 * g + 3) * 37 + dd];
                ((float4*)(qb + (d << 12)))[g] = ov;
                int k0 = sidx[4 * g], k1 = sidx[4 * g + 1];
                int k2 = sidx[4 * g + 2], k3 = sidx[4 * g + 3];
                const float* xr = sxl + d * XLD + 4 * g;
                atomicAdd(&d_sums[(d << 9) + k0], xr[0]);
                atomicAdd(&d_sums[(d << 9) + k1], xr[1]);
                atomicAdd(&d_sums[(d << 9) + k2], xr[2]);
                atomicAdd(&d_sums[(d << 9) + k3], xr[3]);
            }
            __syncthreads();
        }
    }

    grid_sync(tid);

    // ---- fused norm + weight: CTAs 0..63, d = blockIdx, k = tid ----
    if (blockIdx.x < 64) {
        int   cnt  = decode_scalar_int(counter) + 1;
        float bias = 1.f - (float)pow(0.99, (double)cnt);
        int   tr   = decode_scalar_int(training);

        float avg = (ema_c[tid] * 0.99f + (float)d_counts[tid] * 0.01f) / bias;
        float p = avg;
#pragma unroll
        for (int o = 16; o > 0; o >>= 1) p += __shfl_xor_sync(0xffffffffu, p, o);
        float* wred = (float*)sidxh;
        if (lid == 0) wred[wid] = p;
        __syncthreads();
        float nn = 0.f;
#pragma unroll
        for (int i = 0; i < 16; i++) nn += wred[i];

        int j2 = blockIdx.x * 512 + tid;         // [D][K] index: d=blockIdx, k=tid
        if (tr != 0) {
            float norm = (avg + EPSf) / (nn + Kk * EPSf) * nn;
            float nhe  = ema_e[j2] * 0.99f + d_sums[j2] * 0.01f;
            w[(tid << 6) + blockIdx.x] = nhe / (bias * norm);
        } else {
            w[(tid << 6) + blockIdx.x] = emb[(tid << 6) + blockIdx.x];
        }
    }
}

// ---------------------------------------------------------------------------
extern "C" void kernel_launch(void* const* d_in, const int* in_sizes, int n_in,
                              void* d_out, int out_size) {
    const float* x        = (const float*)d_in[0];
    const float* emb      = (const float*)d_in[1];
    const float* ema_c    = (const float*)d_in[2];
    const float* ema_e    = (const float*)d_in[3];
    const int*   counter  = (const int*)d_in[4];
    const int*   training = (const int*)d_in[5];

    float* out = (float*)d_out;
    float* q   = out;                          // [B, D, H, W]
    float* w   = out + (size_t)Bb * DHW;       // [K, D]

    cudaFuncSetAttribute(vq_kernel, cudaFuncAttributeMaxDynamicSharedMemorySize, SM_TOTAL);
    vq_kernel<<<GRID_P, 512, SM_TOTAL>>>(x, emb, ema_c, ema_e, counter, training, q, w);
}

// round 15
// speedup vs baseline: 1.1166x; 1.1166x over previous
#include <cuda_runtime.h>
#include <cuda_fp16.h>
#include <math.h>
#include <stdint.h>

// Problem constants
#define Bb     32
#define Dd     64
#define Kk     512
#define DHW    262144        // D*H*W
#define Nn     131072        // B*H*W
#define EPSf   1e-5f
#define NTILES 1024          // 128-row tiles
#define GRID_P 148           // persistent CTAs

// ---------------------------------------------------------------------------
// Helpers
// ---------------------------------------------------------------------------
__device__ __forceinline__ uint32_t smem_to_u32(const void* p) {
    uint32_t a;
    asm("{ .reg .u64 t; cvta.to.shared.u64 t, %1; cvt.u32.u64 %0, t; }" : "=r"(a) : "l"(p));
    return a;
}
__device__ __forceinline__ void f16_split2(float a, float b, uint32_t& hi, uint32_t& lo) {
    __half ha = __float2half_rn(a), hb = __float2half_rn(b);
    float  ra = a - __half2float(ha), rb = b - __half2float(hb);
    __half la = __float2half_rn(ra), lb = __float2half_rn(rb);
    __half2 h = __halves2half2(ha, hb), l = __halves2half2(la, lb);
    hi = *(uint32_t*)&h;
    lo = *(uint32_t*)&l;
}
__device__ __forceinline__ void mma_f16(float* c, const uint32_t* a, uint32_t b0, uint32_t b1) {
    asm volatile("mma.sync.aligned.m16n8k16.row.col.f32.f16.f16.f32 "
        "{%0,%1,%2,%3}, {%4,%5,%6,%7}, {%8,%9}, {%0,%1,%2,%3};"
        : "+f"(c[0]), "+f"(c[1]), "+f"(c[2]), "+f"(c[3])
        : "r"(a[0]), "r"(a[1]), "r"(a[2]), "r"(a[3]), "r"(b0), "r"(b1));
}
#define CP_ASYNC16(s, g) asm volatile("cp.async.cg.shared.global [%0], [%1], 16;" :: "r"(s), "l"(g))
#define CP_COMMIT()      asm volatile("cp.async.commit_group;" ::: "memory")
#define CP_WAIT0()       asm volatile("cp.async.wait_group 0;" ::: "memory")

// ---------------------------------------------------------------------------
// Scratch
// ---------------------------------------------------------------------------
__device__ float d_ec[Kk];
__device__ int   d_counts[Kk];
__device__ float d_sums[Dd * Kk];
__device__ uint4 g_frag[8192];

// ---------------------------------------------------------------------------
// Kernel A: coalesced prep
// ---------------------------------------------------------------------------
__global__ void prep_kernel(const float* __restrict__ emb) {
    int i = blockIdx.x * 256 + threadIdx.x;       // 0..8191
    ((float4*)d_sums)[i] = make_float4(0.f, 0.f, 0.f, 0.f);
    if (i < Kk) d_counts[i] = 0;

    float4 v = __ldg((const float4*)emb + i);
    int code = i >> 4, kq = i & 15, k = kq << 2;

    float s = v.x * v.x + v.y * v.y + v.z * v.z + v.w * v.w;
#pragma unroll
    for (int o = 1; o <= 8; o <<= 1) s += __shfl_xor_sync(0xffffffffu, s, o);
    if (kq == 0) d_ec[code] = s;

    uint32_t* gf = (uint32_t*)g_frag;
    int nt = code >> 3;
#pragma unroll
    for (int p = 0; p < 2; p++) {
        int   k0 = k + 2 * p;
        float a  = p ? v.z : v.x;
        float b  = p ? v.w : v.y;
        uint32_t hi, lo;
        f16_split2(a, b, hi, lo);
        int rem  = k0 & 15;
        int slot = rem >> 3;
        int sel  = (rem & 7) >> 1;
        int ks   = k0 >> 4;
        int entry = nt * 128 + ks * 32 + ((code & 7) << 2) + sel;
        gf[entry * 4 + slot]     = hi;
        gf[entry * 4 + 2 + slot] = lo;
    }
}

// ---------------------------------------------------------------------------
// SMEM layout (bytes)
// ---------------------------------------------------------------------------
#define XLD       132
#define SM_X0     0
#define SM_X1     33792
#define SM_EC     67584
#define SM_BEST   69632
#define SM_IDXH   71680
#define SM_SIDX   73728
#define SM_SQ     74240
#define SM_FRAG   93184
#define SM_TOTAL  224256

// one n-pair MMA + argmin iteration; 2-way accumulator split:
// accA = hi*hi (chain depth 4), accB = hi*lo + lo*hi (chain depth 8)
#define NP_ONE(NPV) {                                                          \
    int ntA = (qtr << 4) + 2 * (NPV);                                          \
    float accA[4][4] = {{0.f,0.f,0.f,0.f},{0.f,0.f,0.f,0.f},                   \
                        {0.f,0.f,0.f,0.f},{0.f,0.f,0.f,0.f}};                  \
    float accB[4][4] = {{0.f,0.f,0.f,0.f},{0.f,0.f,0.f,0.f},                   \
                        {0.f,0.f,0.f,0.f},{0.f,0.f,0.f,0.f}};                  \
    _Pragma("unroll")                                                          \
    for (int ks = 0; ks < 4; ks++) {                                           \
        uint32_t a0 = sb + SM_FRAG + ((((ntA << 2) + ks) << 5) + lid) * 16;    \
        uint4 bA, bB;                                                          \
        asm volatile("ld.shared.v4.b32 {%0,%1,%2,%3}, [%4];"                   \
            : "=r"(bA.x), "=r"(bA.y), "=r"(bA.z), "=r"(bA.w) : "r"(a0));       \
        asm volatile("ld.shared.v4.b32 {%0,%1,%2,%3}, [%4];"                   \
            : "=r"(bB.x), "=r"(bB.y), "=r"(bB.z), "=r"(bB.w) : "r"(a0 + 2048));\
        const uint32_t* ah0 = &Ahi[ks * 4];                                    \
        const uint32_t* al0 = &Alo[ks * 4];                                    \
        const uint32_t* ah1 = &Ahi[16 + ks * 4];                               \
        const uint32_t* al1 = &Alo[16 + ks * 4];                               \
        mma_f16(accA[0], ah0, bA.x, bA.y);    /* hh */                         \
        mma_f16(accA[1], ah0, bB.x, bB.y);                                     \
        mma_f16(accA[2], ah1, bA.x, bA.y);                                     \
        mma_f16(accA[3], ah1, bB.x, bB.y);                                     \
        mma_f16(accB[0], ah0, bA.z, bA.w);    /* hl */                         \
        mma_f16(accB[1], ah0, bB.z, bB.w);                                     \
        mma_f16(accB[2], ah1, bA.z, bA.w);                                     \
        mma_f16(accB[3], ah1, bB.z, bB.w);                                     \
        mma_f16(accB[0], al0, bA.x, bA.y);    /* lh */                         \
        mma_f16(accB[1], al0, bB.x, bB.y);                                     \
        mma_f16(accB[2], al1, bA.x, bA.y);                                     \
        mma_f16(accB[3], al1, bB.x, bB.y);                                     \
    }                                                                          \
    int base0 = ntA * 8 + 2 * tig;                                             \
    float2 e0 = *(float2*)(sec + base0);                                       \
    float2 e1 = *(float2*)(sec + base0 + 8);                                   \
    float s;                                                                   \
    s = fmaf(accA[0][0] + accB[0][0], -2.f, e0.x); if (s < best[0]) { best[0] = s; idx[0] = base0; }     \
    s = fmaf(accA[0][1] + accB[0][1], -2.f, e0.y); if (s < best[0]) { best[0] = s; idx[0] = base0 + 1; } \
    s = fmaf(accA[0][2] + accB[0][2], -2.f, e0.x); if (s < best[1]) { best[1] = s; idx[1] = base0; }     \
    s = fmaf(accA[0][3] + accB[0][3], -2.f, e0.y); if (s < best[1]) { best[1] = s; idx[1] = base0 + 1; } \
    s = fmaf(accA[1][0] + accB[1][0], -2.f, e1.x); if (s < best[0]) { best[0] = s; idx[0] = base0 + 8; } \
    s = fmaf(accA[1][1] + accB[1][1], -2.f, e1.y); if (s < best[0]) { best[0] = s; idx[0] = base0 + 9; } \
    s = fmaf(accA[1][2] + accB[1][2], -2.f, e1.x); if (s < best[1]) { best[1] = s; idx[1] = base0 + 8; } \
    s = fmaf(accA[1][3] + accB[1][3], -2.f, e1.y); if (s < best[1]) { best[1] = s; idx[1] = base0 + 9; } \
    s = fmaf(accA[2][0] + accB[2][0], -2.f, e0.x); if (s < best[2]) { best[2] = s; idx[2] = base0; }     \
    s = fmaf(accA[2][1] + accB[2][1], -2.f, e0.y); if (s < best[2]) { best[2] = s; idx[2] = base0 + 1; } \
    s = fmaf(accA[2][2] + accB[2][2], -2.f, e0.x); if (s < best[3]) { best[3] = s; idx[3] = base0; }     \
    s = fmaf(accA[2][3] + accB[2][3], -2.f, e0.y); if (s < best[3]) { best[3] = s; idx[3] = base0 + 1; } \
    s = fmaf(accA[3][0] + accB[3][0], -2.f, e1.x); if (s < best[2]) { best[2] = s; idx[2] = base0 + 8; } \
    s = fmaf(accA[3][1] + accB[3][1], -2.f, e1.y); if (s < best[2]) { best[2] = s; idx[2] = base0 + 9; } \
    s = fmaf(accA[3][2] + accB[3][2], -2.f, e1.x); if (s < best[3]) { best[3] = s; idx[3] = base0 + 8; } \
    s = fmaf(accA[3][3] + accB[3][3], -2.f, e1.y); if (s < best[3]) { best[3] = s; idx[3] = base0 + 9; } \
}

// ---------------------------------------------------------------------------
// Kernel B: persistent 3xFP16 mma.sync GEMM; pipelined epilogue (R13 struct)
// ---------------------------------------------------------------------------
__global__ __launch_bounds__(512, 1)
void assign_kernel(const float* __restrict__ x,
                   const float* __restrict__ emb,
                   float* __restrict__ q) {
    extern __shared__ char smem[];
    uint32_t sb = smem_to_u32(smem);
    int tid = threadIdx.x;
    int wid = tid >> 5;
    int lid = tid & 31;
    int grp = lid >> 2;
    int tig = lid & 3;
    int qtr = wid & 3;
    int rws = wid >> 2;

    float* sec   = (float*)(smem + SM_EC);
    float* sbest = (float*)(smem + SM_BEST);
    int*   sidxh = (int*)(smem + SM_IDXH);
    int*   sidx  = (int*)(smem + SM_SIDX);
    float* sq    = (float*)(smem + SM_SQ);

    int er = tid >> 3, ec_ = tid & 7;
    int edd = tid >> 5, eg = tid & 31;

    // ---- prologue ----
#pragma unroll
    for (int jj = 0; jj < 16; jj++) {
        int i = tid + jj * 512;
        CP_ASYNC16(sb + SM_FRAG + i * 16, (const char*)g_frag + i * 16);
    }
    {
        int t0  = blockIdx.x;
        const float* xb = x + (size_t)(t0 >> 5) * DHW + ((t0 & 31) << 7);
#pragma unroll
        for (int jj = 0; jj < 4; jj++) {
            int i = tid + jj * 512;
            int d = i >> 5, r4 = (i & 31) << 2;
            CP_ASYNC16(sb + SM_X0 + (d * XLD + r4) * 4,
                       (const char*)(xb + (d << 12) + r4));
        }
    }
    sec[tid] = d_ec[tid];
    CP_COMMIT();
    CP_WAIT0();
    __syncthreads();

    int j = 0;
    int bp = 0, hwp = 0;
    for (int t = blockIdx.x; t < NTILES; t += GRID_P, j++) {
        float* sxc = (float*)(smem + ((j & 1) ? SM_X1 : SM_X0));
        float* sxp = (float*)(smem + ((j & 1) ? SM_X0 : SM_X1));
        uint32_t sxpb = sb + ((j & 1) ? SM_X0 : SM_X1);
        int b   = t >> 5;
        int hw0 = (t & 31) << 7;
        int tn  = t + GRID_P;
        bool hasPrev = (j > 0);
        float* qbp = q + (size_t)bp * DHW + hwp;

        uint32_t Ahi[32], Alo[32];
#pragma unroll
        for (int mt = 0; mt < 2; mt++) {
            int rb = rws * 32 + mt * 16 + grp;
#pragma unroll
            for (int ks = 0; ks < 4; ks++) {
                int kb = ks * 16 + tig * 2;
                int o  = mt * 16 + ks * 4;
                f16_split2(sxc[kb * XLD + rb],           sxc[(kb + 1) * XLD + rb],
                           Ahi[o + 0], Alo[o + 0]);
                f16_split2(sxc[kb * XLD + rb + 8],       sxc[(kb + 1) * XLD + rb + 8],
                           Ahi[o + 1], Alo[o + 1]);
                f16_split2(sxc[(kb + 8) * XLD + rb],     sxc[(kb + 9) * XLD + rb],
                           Ahi[o + 2], Alo[o + 2]);
                f16_split2(sxc[(kb + 8) * XLD + rb + 8], sxc[(kb + 9) * XLD + rb + 8],
                           Ahi[o + 3], Alo[o + 3]);
            }
        }

        if (!hasPrev && tn < NTILES) {
            const float* xb = x + (size_t)(tn >> 5) * DHW + ((tn & 31) << 7);
#pragma unroll
            for (int jj = 0; jj < 4; jj++) {
                int i = tid + jj * 512;
                int d = i >> 5, r4 = (i & 31) << 2;
                CP_ASYNC16(sxpb + (d * XLD + r4) * 4, (const char*)(xb + (d << 12) + r4));
            }
            CP_COMMIT();
        }

        float best[4] = {3.4e38f, 3.4e38f, 3.4e38f, 3.4e38f};
        int   idx[4]  = {0, 0, 0, 0};
        float4 epv0, epv1;

        NP_ONE(0) NP_ONE(1)
        if (hasPrev) {
            epv0 = __ldg((const float4*)(emb + sidx[er]      * 64 + ec_ * 4));
            epv1 = __ldg((const float4*)(emb + sidx[er + 64] * 64 + ec_ * 4));
        }
        NP_ONE(2) NP_ONE(3)
        if (hasPrev) {
            float* sp0 = sq + er * 37 + ec_ * 4;
            float* sp1 = sq + (er + 64) * 37 + ec_ * 4;
            sp0[0] = epv0.x; sp0[1] = epv0.y; sp0[2] = epv0.z; sp0[3] = epv0.w;
            sp1[0] = epv1.x; sp1[1] = epv1.y; sp1[2] = epv1.z; sp1[3] = epv1.w;
            int k0 = sidx[4 * eg], k1 = sidx[4 * eg + 1];
            int k2 = sidx[4 * eg + 2], k3 = sidx[4 * eg + 3];
#pragma unroll
            for (int hh = 0; hh < 4; hh++) {
                int d = edd + hh * 16;
                const float* xr = sxp + d * XLD + 4 * eg;
                atomicAdd(&d_sums[(d << 9) + k0], xr[0]);
                atomicAdd(&d_sums[(d << 9) + k1], xr[1]);
                atomicAdd(&d_sums[(d << 9) + k2], xr[2]);
                atomicAdd(&d_sums[(d << 9) + k3], xr[3]);
            }
        }
        __syncthreads();
        if (hasPrev && tn < NTILES) {
            const float* xb = x + (size_t)(tn >> 5) * DHW + ((tn & 31) << 7);
#pragma unroll
            for (int jj = 0; jj < 4; jj++) {
                int i = tid + jj * 512;
                int d = i >> 5, r4 = (i & 31) << 2;
                CP_ASYNC16(sxpb + (d * XLD + r4) * 4, (const char*)(xb + (d << 12) + r4));
            }
            CP_COMMIT();
        }
        NP_ONE(4) NP_ONE(5)
        if (hasPrev) {
#pragma unroll
            for (int it = 0; it < 2; it++) {
                int d = edd + it * 16;
                float4 ov;
                ov.x = sq[(4 * eg)     * 37 + d];
                ov.y = sq[(4 * eg + 1) * 37 + d];
                ov.z = sq[(4 * eg + 2) * 37 + d];
                ov.w = sq[(4 * eg + 3) * 37 + d];
                ((float4*)(qbp + (d << 12)))[eg] = ov;
            }
            epv0 = __ldg((const float4*)(emb + sidx[er]      * 64 + 32 + ec_ * 4));
            epv1 = __ldg((const float4*)(emb + sidx[er + 64] * 64 + 32 + ec_ * 4));
        }
        __syncthreads();
        NP_ONE(6) NP_ONE(7)
        if (hasPrev) {
            float* sp0 = sq + er * 37 + ec_ * 4;
            float* sp1 = sq + (er + 64) * 37 + ec_ * 4;
            sp0[0] = epv0.x; sp0[1] = epv0.y; sp0[2] = epv0.z; sp0[3] = epv0.w;
            sp1[0] = epv1.x; sp1[1] = epv1.y; sp1[2] = epv1.z; sp1[3] = epv1.w;
        }
        __syncthreads();
        if (hasPrev) {
#pragma unroll
            for (int it = 0; it < 2; it++) {
                int dd2 = edd + it * 16;
                int d = 32 + dd2;
                float4 ov;
                ov.x = sq[(4 * eg)     * 37 + dd2];
                ov.y = sq[(4 * eg + 1) * 37 + dd2];
                ov.z = sq[(4 * eg + 2) * 37 + dd2];
                ov.w = sq[(4 * eg + 3) * 37 + dd2];
                ((float4*)(qbp + (d << 12)))[eg] = ov;
            }
        }

#pragma unroll
        for (int v = 0; v < 4; v++) {
#pragma unroll
            for (int o = 1; o <= 2; o <<= 1) {
                float ob = __shfl_xor_sync(0xffffffffu, best[v], o);
                int   oi = __shfl_xor_sync(0xffffffffu, idx[v], o);
                if (ob < best[v] || (ob == best[v] && oi < idx[v])) { best[v] = ob; idx[v] = oi; }
            }
        }
        if (tig == 0) {
            int rl = rws * 32 + grp;
            sbest[qtr * 128 + rl]      = best[0];
            sbest[qtr * 128 + rl + 8]  = best[1];
            sbest[qtr * 128 + rl + 16] = best[2];
            sbest[qtr * 128 + rl + 24] = best[3];
            sidxh[qtr * 128 + rl]      = idx[0];
            sidxh[qtr * 128 + rl + 8]  = idx[1];
            sidxh[qtr * 128 + rl + 16] = idx[2];
            sidxh[qtr * 128 + rl + 24] = idx[3];
        }
        __syncthreads();
        if (tid < 128) {
            float bb = sbest[tid]; int ii = sidxh[tid];
#pragma unroll
            for (int qq = 1; qq < 4; qq++) {
                float b2 = sbest[qq * 128 + tid];
                if (b2 < bb) { bb = b2; ii = sidxh[qq * 128 + tid]; }
            }
            sidx[tid] = ii;
            atomicAdd(&d_counts[ii], 1);
        }
        bp = b; hwp = hw0;
        CP_WAIT0();
        __syncthreads();
    }

    // ---- final tile epilogue ----
    {
        float* sxl = (float*)(smem + (((j - 1) & 1) ? SM_X1 : SM_X0));
        float* qb  = q + (size_t)bp * DHW + hwp;
#pragma unroll
        for (int pass = 0; pass < 2; pass++) {
#pragma unroll
            for (int it = 0; it < 2; it++) {
                int item = tid + it * 512;
                int r = item >> 3, c = item & 7;
                int ki = sidx[r];
                float4 ev = __ldg((const float4*)(emb + ki * 64 + pass * 32 + c * 4));
                float* sp = sq + r * 37 + c * 4;
                sp[0] = ev.x; sp[1] = ev.y; sp[2] = ev.z; sp[3] = ev.w;
            }
            __syncthreads();
#pragma unroll
            for (int it = 0; it < 2; it++) {
                int item = tid + it * 512;
                int dd = item >> 5, g = item & 31;
                int d  = pass * 32 + dd;
                float4 ov;
                ov.x = sq[(4 * g)     * 37 + dd];
                ov.y = sq[(4 * g + 1) * 37 + dd];
                ov.z = sq[(4 * g + 2) * 37 + dd];
                ov.w = sq[(4 * g + 3) * 37 + dd];
                ((float4*)(qb + (d << 12)))[g] = ov;
                int k0 = sidx[4 * g], k1 = sidx[4 * g + 1];
                int k2 = sidx[4 * g + 2], k3 = sidx[4 * g + 3];
                const float* xr = sxl + d * XLD + 4 * g;
                atomicAdd(&d_sums[(d << 9) + k0], xr[0]);
                atomicAdd(&d_sums[(d << 9) + k1], xr[1]);
                atomicAdd(&d_sums[(d << 9) + k2], xr[2]);
                atomicAdd(&d_sums[(d << 9) + k3], xr[3]);
            }
            __syncthreads();
        }
    }
}

// ---------------------------------------------------------------------------
// Kernel C: fused norm + weight
// ---------------------------------------------------------------------------
__device__ __forceinline__ int decode_scalar_int(const int* p) {
    int v = *p;
    if (v >= 0 && v < 1000000) return v;
    return (int)__int_as_float(v);
}

__global__ __launch_bounds__(256)
void weight_kernel(const float* __restrict__ ema_c,
                   const float* __restrict__ ema_e,
                   const float* __restrict__ emb,
                   const int* __restrict__ counter,
                   const int* __restrict__ training,
                   float* __restrict__ w) {
    __shared__ float savg[Kk];
    __shared__ float wsum[8];
    int tid = threadIdx.x;

    int   cnt  = decode_scalar_int(counter) + 1;
    float bias = 1.f - (float)pow(0.99, (double)cnt);

    float partial = 0.f;
#pragma unroll
    for (int kk = tid; kk < Kk; kk += 256) {
        float avg = (ema_c[kk] * 0.99f + (float)d_counts[kk] * 0.01f) / bias;
        savg[kk] = avg;
        partial += avg;
    }
#pragma unroll
    for (int o = 16; o > 0; o >>= 1) partial += __shfl_xor_sync(0xffffffffu, partial, o);
    if ((tid & 31) == 0) wsum[tid >> 5] = partial;
    __syncthreads();
    float nn = 0.f;
#pragma unroll
    for (int i = 0; i < 8; i++) nn += wsum[i];

    int j = blockIdx.x * 256 + tid;
    int d = j >> 9;
    int k = j & 511;

    int tr = decode_scalar_int(training);
    if (tr != 0) {
        float norm = (savg[k] + EPSf) / (nn + Kk * EPSf) * nn;
        float sc   = 1.f / (bias * norm);
        float nhe  = ema_e[j] * 0.99f + d_sums[j] * 0.01f;
        w[(k << 6) + d] = nhe * sc;
    } else {
        w[(k << 6) + d] = emb[(k << 6) + d];
    }
}

// ---------------------------------------------------------------------------
extern "C" void kernel_launch(void* const* d_in, const int* in_sizes, int n_in,
                              void* d_out, int out_size) {
    const float* x        = (const float*)d_in[0];
    const float* emb      = (const float*)d_in[1];
    const float* ema_c    = (const float*)d_in[2];
    const float* ema_e    = (const float*)d_in[3];
    const int*   counter  = (const int*)d_in[4];
    const int*   training = (const int*)d_in[5];

    float* out = (float*)d_out;
    float* q   = out;                          // [B, D, H, W]
    float* w   = out + (size_t)Bb * DHW;       // [K, D]

    cudaFuncSetAttribute(assign_kernel, cudaFuncAttributeMaxDynamicSharedMemorySize, SM_TOTAL);

    prep_kernel  <<<32,     256>>>(emb);
    assign_kernel<<<GRID_P, 512, SM_TOTAL>>>(x, emb, q);
    weight_kernel<<<Dd * Kk / 256, 256>>>(ema_c, ema_e, emb, counter, training, w);
}

// round 16
// speedup vs baseline: 1.1810x; 1.0577x over previous
#include <cuda_runtime.h>
#include <cuda_fp16.h>
#include <math.h>
#include <stdint.h>

// Problem constants
#define Bb     32
#define Dd     64
#define Kk     512
#define DHW    262144        // D*H*W
#define Nn     131072        // B*H*W
#define EPSf   1e-5f
#define NTILES 1024          // 128-row tiles
#define GRID_P 148           // persistent CTAs

// ---------------------------------------------------------------------------
// Helpers
// ---------------------------------------------------------------------------
__device__ __forceinline__ uint32_t smem_to_u32(const void* p) {
    uint32_t a;
    asm("{ .reg .u64 t; cvta.to.shared.u64 t, %1; cvt.u32.u64 %0, t; }" : "=r"(a) : "l"(p));
    return a;
}
// fp16 split of a pair of floats: hi = h2(fp16(a), fp16(b)), lo = h2 of residuals
__device__ __forceinline__ void f16_split2(float a, float b, uint32_t& hi, uint32_t& lo) {
    __half ha = __float2half_rn(a), hb = __float2half_rn(b);
    float  ra = a - __half2float(ha), rb = b - __half2float(hb);
    __half la = __float2half_rn(ra), lb = __float2half_rn(rb);
    __half2 h = __halves2half2(ha, hb), l = __halves2half2(la, lb);
    hi = *(uint32_t*)&h;
    lo = *(uint32_t*)&l;
}
// D = A(16x16 f16, row) * B(16x8 f16, col) + D, fp32 accum
__device__ __forceinline__ void mma_f16(float* c, const uint32_t* a, uint32_t b0, uint32_t b1) {
    asm volatile("mma.sync.aligned.m16n8k16.row.col.f32.f16.f16.f32 "
        "{%0,%1,%2,%3}, {%4,%5,%6,%7}, {%8,%9}, {%0,%1,%2,%3};"
        : "+f"(c[0]), "+f"(c[1]), "+f"(c[2]), "+f"(c[3])
        : "r"(a[0]), "r"(a[1]), "r"(a[2]), "r"(a[3]), "r"(b0), "r"(b1));
}
#define CP_ASYNC16(s, g) asm volatile("cp.async.cg.shared.global [%0], [%1], 16;" :: "r"(s), "l"(g))
#define CP_COMMIT()      asm volatile("cp.async.commit_group;" ::: "memory")
#define CP_WAIT0()       asm volatile("cp.async.wait_group 0;" ::: "memory")

// ---------------------------------------------------------------------------
// Scratch
// ---------------------------------------------------------------------------
__device__ float d_ec[Kk];
__device__ int   d_counts[Kk];
__device__ float d_sums[Dd * Kk];
// codebook in fp16-split mma-fragment order:
// [ntile(64)][kstep(4)][lane(32)] -> {b0hi, b1hi, b0lo, b1lo}
__device__ uint4 g_frag[8192];

// ---------------------------------------------------------------------------
// Kernel A: coalesced prep — zero sums/counts, ||e_k||^2, fragment packing.
// ---------------------------------------------------------------------------
__global__ void prep_kernel(const float* __restrict__ emb) {
    int i = blockIdx.x * 256 + threadIdx.x;       // 0..8191
    ((float4*)d_sums)[i] = make_float4(0.f, 0.f, 0.f, 0.f);
    if (i < Kk) d_counts[i] = 0;

    float4 v = __ldg((const float4*)emb + i);
    int code = i >> 4, kq = i & 15, k = kq << 2;

    float s = v.x * v.x + v.y * v.y + v.z * v.z + v.w * v.w;
#pragma unroll
    for (int o = 1; o <= 8; o <<= 1) s += __shfl_xor_sync(0xffffffffu, s, o);
    if (kq == 0) d_ec[code] = s;

    uint32_t* gf = (uint32_t*)g_frag;
    int nt = code >> 3;
#pragma unroll
    for (int p = 0; p < 2; p++) {
        int   k0 = k + 2 * p;
        float a  = p ? v.z : v.x;
        float b  = p ? v.w : v.y;
        uint32_t hi, lo;
        f16_split2(a, b, hi, lo);
        int rem  = k0 & 15;
        int slot = rem >> 3;
        int sel  = (rem & 7) >> 1;
        int ks   = k0 >> 4;
        int entry = nt * 128 + ks * 32 + ((code & 7) << 2) + sel;
        gf[entry * 4 + slot]     = hi;
        gf[entry * 4 + 2 + slot] = lo;
    }
}

// ---------------------------------------------------------------------------
// SMEM layout (bytes): x tiles [d(64)][132 f32], double buffered
// ---------------------------------------------------------------------------
#define XLD       132
#define SM_X0     0                        // 33792
#define SM_X1     33792                    // 33792
#define SM_EC     67584                    // 2048
#define SM_BEST   69632                    // 2048
#define SM_IDXH   71680                    // 2048
#define SM_SIDX   73728                    // 512
#define SM_SQ     74240                    // 18944
#define SM_FRAG   93184                    // 131072
#define SM_TOTAL  224256

// one n-pair MMA + argmin iteration (np = NPV) — R13 single-accumulator form
#define NP_ONE(NPV) {                                                          \
    int ntA = (qtr << 4) + 2 * (NPV);                                          \
    float acc[4][4] = {{0.f,0.f,0.f,0.f},{0.f,0.f,0.f,0.f},                    \
                       {0.f,0.f,0.f,0.f},{0.f,0.f,0.f,0.f}};                   \
    _Pragma("unroll")                                                          \
    for (int ks = 0; ks < 4; ks++) {                                           \
        uint32_t a0 = sb + SM_FRAG + ((((ntA << 2) + ks) << 5) + lid) * 16;    \
        uint4 bA, bB;                                                          \
        asm volatile("ld.shared.v4.b32 {%0,%1,%2,%3}, [%4];"                   \
            : "=r"(bA.x), "=r"(bA.y), "=r"(bA.z), "=r"(bA.w) : "r"(a0));       \
        asm volatile("ld.shared.v4.b32 {%0,%1,%2,%3}, [%4];"                   \
            : "=r"(bB.x), "=r"(bB.y), "=r"(bB.z), "=r"(bB.w) : "r"(a0 + 2048));\
        const uint32_t* ah0 = &Ahi[ks * 4];                                    \
        const uint32_t* al0 = &Alo[ks * 4];                                    \
        const uint32_t* ah1 = &Ahi[16 + ks * 4];                               \
        const uint32_t* al1 = &Alo[16 + ks * 4];                               \
        mma_f16(acc[0], ah0, bA.x, bA.y);                                      \
        mma_f16(acc[1], ah0, bB.x, bB.y);                                      \
        mma_f16(acc[2], ah1, bA.x, bA.y);                                      \
        mma_f16(acc[3], ah1, bB.x, bB.y);                                      \
        mma_f16(acc[0], ah0, bA.z, bA.w);                                      \
        mma_f16(acc[1], ah0, bB.z, bB.w);                                      \
        mma_f16(acc[2], ah1, bA.z, bA.w);                                      \
        mma_f16(acc[3], ah1, bB.z, bB.w);                                      \
        mma_f16(acc[0], al0, bA.x, bA.y);                                      \
        mma_f16(acc[1], al0, bB.x, bB.y);                                      \
        mma_f16(acc[2], al1, bA.x, bA.y);                                      \
        mma_f16(acc[3], al1, bB.x, bB.y);                                      \
    }                                                                          \
    int base0 = ntA * 8 + 2 * tig;                                             \
    float2 e0 = *(float2*)(sec + base0);                                       \
    float2 e1 = *(float2*)(sec + base0 + 8);                                   \
    float s;                                                                   \
    s = fmaf(acc[0][0], -2.f, e0.x); if (s < best[0]) { best[0] = s; idx[0] = base0; }     \
    s = fmaf(acc[0][1], -2.f, e0.y); if (s < best[0]) { best[0] = s; idx[0] = base0 + 1; } \
    s = fmaf(acc[0][2], -2.f, e0.x); if (s < best[1]) { best[1] = s; idx[1] = base0; }     \
    s = fmaf(acc[0][3], -2.f, e0.y); if (s < best[1]) { best[1] = s; idx[1] = base0 + 1; } \
    s = fmaf(acc[1][0], -2.f, e1.x); if (s < best[0]) { best[0] = s; idx[0] = base0 + 8; } \
    s = fmaf(acc[1][1], -2.f, e1.y); if (s < best[0]) { best[0] = s; idx[0] = base0 + 9; } \
    s = fmaf(acc[1][2], -2.f, e1.x); if (s < best[1]) { best[1] = s; idx[1] = base0 + 8; } \
    s = fmaf(acc[1][3], -2.f, e1.y); if (s < best[1]) { best[1] = s; idx[1] = base0 + 9; } \
    s = fmaf(acc[2][0], -2.f, e0.x); if (s < best[2]) { best[2] = s; idx[2] = base0; }     \
    s = fmaf(acc[2][1], -2.f, e0.y); if (s < best[2]) { best[2] = s; idx[2] = base0 + 1; } \
    s = fmaf(acc[2][2], -2.f, e0.x); if (s < best[3]) { best[3] = s; idx[3] = base0; }     \
    s = fmaf(acc[2][3], -2.f, e0.y); if (s < best[3]) { best[3] = s; idx[3] = base0 + 1; } \
    s = fmaf(acc[3][0], -2.f, e1.x); if (s < best[2]) { best[2] = s; idx[2] = base0 + 8; } \
    s = fmaf(acc[3][1], -2.f, e1.y); if (s < best[2]) { best[2] = s; idx[2] = base0 + 9; } \
    s = fmaf(acc[3][2], -2.f, e1.x); if (s < best[3]) { best[3] = s; idx[3] = base0 + 8; } \
    s = fmaf(acc[3][3], -2.f, e1.y); if (s < best[3]) { best[3] = s; idx[3] = base0 + 9; } \
}

// ---------------------------------------------------------------------------
// Kernel B: persistent 3xFP16 mma.sync GEMM; epilogue of tile j-1 pipelined
// into the MMA loop of tile j. 148 CTAs x 512 threads.  (R13 verbatim)
// ---------------------------------------------------------------------------
__global__ __launch_bounds__(512, 1)
void assign_kernel(const float* __restrict__ x,
                   const float* __restrict__ emb,
                   float* __restrict__ q) {
    extern __shared__ char smem[];
    uint32_t sb = smem_to_u32(smem);
    int tid = threadIdx.x;
    int wid = tid >> 5;
    int lid = tid & 31;
    int grp = lid >> 2;
    int tig = lid & 3;
    int qtr = wid & 3;
    int rws = wid >> 2;

    float* sec   = (float*)(smem + SM_EC);
    float* sbest = (float*)(smem + SM_BEST);
    int*   sidxh = (int*)(smem + SM_IDXH);
    int*   sidx  = (int*)(smem + SM_SIDX);
    float* sq    = (float*)(smem + SM_SQ);

    int er = tid >> 3, ec_ = tid & 7;
    int edd = tid >> 5, eg = tid & 31;

    // ---- prologue ----
#pragma unroll
    for (int jj = 0; jj < 16; jj++) {
        int i = tid + jj * 512;
        CP_ASYNC16(sb + SM_FRAG + i * 16, (const char*)g_frag + i * 16);
    }
    {
        int t0  = blockIdx.x;
        const float* xb = x + (size_t)(t0 >> 5) * DHW + ((t0 & 31) << 7);
#pragma unroll
        for (int jj = 0; jj < 4; jj++) {
            int i = tid + jj * 512;
            int d = i >> 5, r4 = (i & 31) << 2;
            CP_ASYNC16(sb + SM_X0 + (d * XLD + r4) * 4,
                       (const char*)(xb + (d << 12) + r4));
        }
    }
    sec[tid] = d_ec[tid];
    CP_COMMIT();
    CP_WAIT0();
    __syncthreads();

    int j = 0;
    int bp = 0, hwp = 0;
    for (int t = blockIdx.x; t < NTILES; t += GRID_P, j++) {
        float* sxc = (float*)(smem + ((j & 1) ? SM_X1 : SM_X0));
        float* sxp = (float*)(smem + ((j & 1) ? SM_X0 : SM_X1));
        uint32_t sxpb = sb + ((j & 1) ? SM_X0 : SM_X1);
        int b   = t >> 5;
        int hw0 = (t & 31) << 7;
        int tn  = t + GRID_P;
        bool hasPrev = (j > 0);
        float* qbp = q + (size_t)bp * DHW + hwp;

        uint32_t Ahi[32], Alo[32];
#pragma unroll
        for (int mt = 0; mt < 2; mt++) {
            int rb = rws * 32 + mt * 16 + grp;
#pragma unroll
            for (int ks = 0; ks < 4; ks++) {
                int kb = ks * 16 + tig * 2;
                int o  = mt * 16 + ks * 4;
                f16_split2(sxc[kb * XLD + rb],           sxc[(kb + 1) * XLD + rb],
                           Ahi[o + 0], Alo[o + 0]);
                f16_split2(sxc[kb * XLD + rb + 8],       sxc[(kb + 1) * XLD + rb + 8],
                           Ahi[o + 1], Alo[o + 1]);
                f16_split2(sxc[(kb + 8) * XLD + rb],     sxc[(kb + 9) * XLD + rb],
                           Ahi[o + 2], Alo[o + 2]);
                f16_split2(sxc[(kb + 8) * XLD + rb + 8], sxc[(kb + 9) * XLD + rb + 8],
                           Ahi[o + 3], Alo[o + 3]);
            }
        }

        if (!hasPrev && tn < NTILES) {
            const float* xb = x + (size_t)(tn >> 5) * DHW + ((tn & 31) << 7);
#pragma unroll
            for (int jj = 0; jj < 4; jj++) {
                int i = tid + jj * 512;
                int d = i >> 5, r4 = (i & 31) << 2;
                CP_ASYNC16(sxpb + (d * XLD + r4) * 4, (const char*)(xb + (d << 12) + r4));
            }
            CP_COMMIT();
        }

        float best[4] = {3.4e38f, 3.4e38f, 3.4e38f, 3.4e38f};
        int   idx[4]  = {0, 0, 0, 0};
        float4 epv0, epv1;

        NP_ONE(0) NP_ONE(1)
        if (hasPrev) {
            epv0 = __ldg((const float4*)(emb + sidx[er]      * 64 + ec_ * 4));
            epv1 = __ldg((const float4*)(emb + sidx[er + 64] * 64 + ec_ * 4));
        }
        NP_ONE(2) NP_ONE(3)
        if (hasPrev) {
            float* sp0 = sq + er * 37 + ec_ * 4;
            float* sp1 = sq + (er + 64) * 37 + ec_ * 4;
            sp0[0] = epv0.x; sp0[1] = epv0.y; sp0[2] = epv0.z; sp0[3] = epv0.w;
            sp1[0] = epv1.x; sp1[1] = epv1.y; sp1[2] = epv1.z; sp1[3] = epv1.w;
            int k0 = sidx[4 * eg], k1 = sidx[4 * eg + 1];
            int k2 = sidx[4 * eg + 2], k3 = sidx[4 * eg + 3];
#pragma unroll
            for (int hh = 0; hh < 4; hh++) {
                int d = edd + hh * 16;
                const float* xr = sxp + d * XLD + 4 * eg;
                atomicAdd(&d_sums[(d << 9) + k0], xr[0]);
                atomicAdd(&d_sums[(d << 9) + k1], xr[1]);
                atomicAdd(&d_sums[(d << 9) + k2], xr[2]);
                atomicAdd(&d_sums[(d << 9) + k3], xr[3]);
            }
        }
        __syncthreads();
        if (hasPrev && tn < NTILES) {
            const float* xb = x + (size_t)(tn >> 5) * DHW + ((tn & 31) << 7);
#pragma unroll
            for (int jj = 0; jj < 4; jj++) {
                int i = tid + jj * 512;
                int d = i >> 5, r4 = (i & 31) << 2;
                CP_ASYNC16(sxpb + (d * XLD + r4) * 4, (const char*)(xb + (d << 12) + r4));
            }
            CP_COMMIT();
        }
        NP_ONE(4) NP_ONE(5)
        if (hasPrev) {
#pragma unroll
            for (int it = 0; it < 2; it++) {
                int d = edd + it * 16;
                float4 ov;
                ov.x = sq[(4 * eg)     * 37 + d];
                ov.y = sq[(4 * eg + 1) * 37 + d];
                ov.z = sq[(4 * eg + 2) * 37 + d];
                ov.w = sq[(4 * eg + 3) * 37 + d];
                ((float4*)(qbp + (d << 12)))[eg] = ov;
            }
            epv0 = __ldg((const float4*)(emb + sidx[er]      * 64 + 32 + ec_ * 4));
            epv1 = __ldg((const float4*)(emb + sidx[er + 64] * 64 + 32 + ec_ * 4));
        }
        __syncthreads();
        NP_ONE(6) NP_ONE(7)
        if (hasPrev) {
            float* sp0 = sq + er * 37 + ec_ * 4;
            float* sp1 = sq + (er + 64) * 37 + ec_ * 4;
            sp0[0] = epv0.x; sp0[1] = epv0.y; sp0[2] = epv0.z; sp0[3] = epv0.w;
            sp1[0] = epv1.x; sp1[1] = epv1.y; sp1[2] = epv1.z; sp1[3] = epv1.w;
        }
        __syncthreads();
        if (hasPrev) {
#pragma unroll
            for (int it = 0; it < 2; it++) {
                int dd2 = edd + it * 16;
                int d = 32 + dd2;
                float4 ov;
                ov.x = sq[(4 * eg)     * 37 + dd2];
                ov.y = sq[(4 * eg + 1) * 37 + dd2];
                ov.z = sq[(4 * eg + 2) * 37 + dd2];
                ov.w = sq[(4 * eg + 3) * 37 + dd2];
                ((float4*)(qbp + (d << 12)))[eg] = ov;
            }
        }

#pragma unroll
        for (int v = 0; v < 4; v++) {
#pragma unroll
            for (int o = 1; o <= 2; o <<= 1) {
                float ob = __shfl_xor_sync(0xffffffffu, best[v], o);
                int   oi = __shfl_xor_sync(0xffffffffu, idx[v], o);
                if (ob < best[v] || (ob == best[v] && oi < idx[v])) { best[v] = ob; idx[v] = oi; }
            }
        }
        if (tig == 0) {
            int rl = rws * 32 + grp;
            sbest[qtr * 128 + rl]      = best[0];
            sbest[qtr * 128 + rl + 8]  = best[1];
            sbest[qtr * 128 + rl + 16] = best[2];
            sbest[qtr * 128 + rl + 24] = best[3];
            sidxh[qtr * 128 + rl]      = idx[0];
            sidxh[qtr * 128 + rl + 8]  = idx[1];
            sidxh[qtr * 128 + rl + 16] = idx[2];
            sidxh[qtr * 128 + rl + 24] = idx[3];
        }
        __syncthreads();
        if (tid < 128) {
            float bb = sbest[tid]; int ii = sidxh[tid];
#pragma unroll
            for (int qq = 1; qq < 4; qq++) {
                float b2 = sbest[qq * 128 + tid];
                if (b2 < bb) { bb = b2; ii = sidxh[qq * 128 + tid]; }
            }
            sidx[tid] = ii;
            atomicAdd(&d_counts[ii], 1);
        }
        bp = b; hwp = hw0;
        CP_WAIT0();
        __syncthreads();
    }

    // ---- final tile epilogue ----
    {
        float* sxl = (float*)(smem + (((j - 1) & 1) ? SM_X1 : SM_X0));
        float* qb  = q + (size_t)bp * DHW + hwp;
#pragma unroll
        for (int pass = 0; pass < 2; pass++) {
#pragma unroll
            for (int it = 0; it < 2; it++) {
                int item = tid + it * 512;
                int r = item >> 3, c = item & 7;
                int ki = sidx[r];
                float4 ev = __ldg((const float4*)(emb + ki * 64 + pass * 32 + c * 4));
                float* sp = sq + r * 37 + c * 4;
                sp[0] = ev.x; sp[1] = ev.y; sp[2] = ev.z; sp[3] = ev.w;
            }
            __syncthreads();
#pragma unroll
            for (int it = 0; it < 2; it++) {
                int item = tid + it * 512;
                int dd = item >> 5, g = item & 31;
                int d  = pass * 32 + dd;
                float4 ov;
                ov.x = sq[(4 * g)     * 37 + dd];
                ov.y = sq[(4 * g + 1) * 37 + dd];
                ov.z = sq[(4 * g + 2) * 37 + dd];
                ov.w = sq[(4 * g + 3) * 37 + dd];
                ((float4*)(qb + (d << 12)))[g] = ov;
                int k0 = sidx[4 * g], k1 = sidx[4 * g + 1];
                int k2 = sidx[4 * g + 2], k3 = sidx[4 * g + 3];
                const float* xr = sxl + d * XLD + 4 * g;
                atomicAdd(&d_sums[(d << 9) + k0], xr[0]);
                atomicAdd(&d_sums[(d << 9) + k1], xr[1]);
                atomicAdd(&d_sums[(d << 9) + k2], xr[2]);
                atomicAdd(&d_sums[(d << 9) + k3], xr[3]);
            }
            __syncthreads();
        }
    }
}

// ---------------------------------------------------------------------------
// Kernel C: fused norm + weight. 64 CTAs x 512: d = blockIdx, k = tid, so
// each thread's own counts-EMA value is its norm input (no staging array).
// ---------------------------------------------------------------------------
__device__ __forceinline__ int decode_scalar_int(const int* p) {
    int v = *p;
    if (v >= 0 && v < 1000000) return v;
    return (int)__int_as_float(v);
}

__global__ __launch_bounds__(512)
void weight_kernel(const float* __restrict__ ema_c,
                   const float* __restrict__ ema_e,
                   const float* __restrict__ emb,
                   const int* __restrict__ counter,
                   const int* __restrict__ training,
                   float* __restrict__ w) {
    __shared__ float wsum[16];
    int tid = threadIdx.x;     // = k
    int d   = blockIdx.x;

    int   cnt  = decode_scalar_int(counter) + 1;
    float bias = 1.f - (float)pow(0.99, (double)cnt);

    float avg = (ema_c[tid] * 0.99f + (float)d_counts[tid] * 0.01f) / bias;

    float p = avg;
#pragma unroll
    for (int o = 16; o > 0; o >>= 1) p += __shfl_xor_sync(0xffffffffu, p, o);
    if ((tid & 31) == 0) wsum[tid >> 5] = p;
    __syncthreads();
    float nn = 0.f;
#pragma unroll
    for (int i = 0; i < 16; i++) nn += wsum[i];   // same order in every thread

    int j = d * 512 + tid;     // [D][K] linear index
    int tr = decode_scalar_int(training);
    if (tr != 0) {
        float norm = (avg + EPSf) / (nn + Kk * EPSf) * nn;
        float nhe  = ema_e[j] * 0.99f + d_sums[j] * 0.01f;
        w[(tid << 6) + d] = nhe / (bias * norm);
    } else {
        w[(tid << 6) + d] = emb[(tid << 6) + d];
    }
}

// ---------------------------------------------------------------------------
extern "C" void kernel_launch(void* const* d_in, const int* in_sizes, int n_in,
                              void* d_out, int out_size) {
    const float* x        = (const float*)d_in[0];
    const float* emb      = (const float*)d_in[1];
    const float* ema_c    = (const float*)d_in[2];
    const float* ema_e    = (const float*)d_in[3];
    const int*   counter  = (const int*)d_in[4];
    const int*   training = (const int*)d_in[5];

    float* out = (float*)d_out;
    float* q   = out;                          // [B, D, H, W]
    float* w   = out + (size_t)Bb * DHW;       // [K, D]

    cudaFuncSetAttribute(assign_kernel, cudaFuncAttributeMaxDynamicSharedMemorySize, SM_TOTAL);

    prep_kernel  <<<32,     256>>>(emb);
    assign_kernel<<<GRID_P, 512, SM_TOTAL>>>(x, emb, q);
    weight_kernel<<<Dd,     512>>>(ema_c, ema_e, emb, counter, training, w);
}